// round 9
// baseline (speedup 1.0000x reference)
#include <cuda_runtime.h>

#define NN 512
#define CC 16
#define LTL 3
#define AGG_IN 1028
#define TPB 256            // 64 edges per CTA (4 threads per edge)
#define NCHUNK 8           // chunks per q

// scratch (no allocation allowed)
__device__ float g_part[NN * 3 * NCHUNK];  // per-(q,k,chunk) aggregator partials
__device__ unsigned g_cnt[NN];             // arrival counters (self-resetting)
__device__ float g_act[2][NN];             // ping-pong activations

__device__ __forceinline__ float tanh_e(float x) {
    x = fminf(fmaxf(x, -15.0f), 15.0f);
    float e = __expf(2.0f * x);
    return __fdividef(e - 1.0f, e + 1.0f);
}

// ---------------------------------------------------------------------------
// Edge kernel, 4 threads per edge, no smem staging.
// Lane tsub=t&3 owns channel group c in [4*tsub, 4*tsub+4):
//   vW/vb loads are perfectly coalesced (addr = base + t*16B),
//   sW1 loads touch 8 lines/warp-instr (vs 32 for 1-thread-per-edge direct).
// h1 partials & s reduced across the 4 lanes via shfl_xor (deterministic).
// Fused aW1*s partials + last-arriving-CTA epilogue per q (as R8).
// ---------------------------------------------------------------------------
__global__ __launch_bounds__(TPB) void edge_kernel(
    const float* __restrict__ a_ext, int in_buf, int out_buf, int l,
    float* __restrict__ dout,
    const float* __restrict__ vW,  const float* __restrict__ vb,
    const float* __restrict__ sW1, const float* __restrict__ sb1,
    const float* __restrict__ sW2, const float* __restrict__ sb2,
    const float* __restrict__ aW1, const float* __restrict__ ab1,
    const float* __restrict__ aW2, const float* __restrict__ ab2)
{
    __shared__ float red[3][TPB / 32];

    const int t     = threadIdx.x;
    const int cta   = blockIdx.x;
    const int q     = cta >> 3;
    const int chunk = cta & 7;
    const int eidx  = t >> 2;          // edge within chunk (0..63)
    const int tsub  = t & 3;           // lane within edge group
    const int p     = (chunk << 6) + eidx;
    const size_t e  = (size_t)q * NN + p;

    const float* a_in = a_ext ? a_ext : g_act[in_buf];

    // --- epilogue prefetch (thread 0 only; latency hidden under the stream) ---
    float oh[3], eb1[3], ew2[3], eb2 = 0.f;
    if (t == 0) {
        #pragma unroll
        for (int k = 0; k < 3; ++k) {
            const float* row = aW1 + ((size_t)q * 3 + k) * AGG_IN;
            oh[k]  = __ldg(&row[NN + l + 1]) + __ldg(&row[NN + 4 + q]); // one-hots
            eb1[k] = __ldg(&ab1[q * 3 + k]);
            ew2[k] = __ldg(&aW2[q * 3 + k]);
        }
        eb2 = __ldg(&ab2[q]);
    }

    // --- issue ALL loads up-front (independent -> max MLP) ---
    const float ap = __ldg(&a_in[p]);
    const float4 w4  = __ldg((const float4*)vW  + e * 4 + tsub);
    const float4 b4  = __ldg((const float4*)vb  + e * 4 + tsub);
    const float4 s10 = __ldg((const float4*)sW1 + e * 12 + 0 + tsub);
    const float4 s11 = __ldg((const float4*)sW1 + e * 12 + 4 + tsub);
    const float4 s12 = __ldg((const float4*)sW1 + e * 12 + 8 + tsub);
    // lane tsub<3 carries b1[tsub]; lane 3 carries b2
    const float b1v = (tsub < 3) ? __ldg(&sb1[e * 3 + tsub]) : __ldg(&sb2[e]);
    const float w2v = (tsub < 3) ? __ldg(&sW2[e * 3 + tsub]) : 0.f;
    const float awv = (tsub < 3) ? __ldg(&aW1[((size_t)q * 3 + tsub) * AGG_IN + p]) : 0.f;

    // --- VEC: f[c] = tanh(ap*vW[c] + vb[c]) for this lane's 4 channels ---
    const float fx = tanh_e(fmaf(ap, w4.x, b4.x));
    const float fy = tanh_e(fmaf(ap, w4.y, b4.y));
    const float fz = tanh_e(fmaf(ap, w4.z, b4.z));
    const float fw = tanh_e(fmaf(ap, w4.w, b4.w));

    // --- Synapse Linear(16->3): per-lane partial dot over 4 channels ---
    float p0 = fmaf(s10.x, fx, fmaf(s10.y, fy, fmaf(s10.z, fz, s10.w * fw)));
    float p1 = fmaf(s11.x, fx, fmaf(s11.y, fy, fmaf(s11.z, fz, s11.w * fw)));
    float p2 = fmaf(s12.x, fx, fmaf(s12.y, fy, fmaf(s12.z, fz, s12.w * fw)));
    // fold in b1 (lane tsub holds b1[tsub]; lane 3 holds b2 -> never selected)
    p0 += (tsub == 0) ? b1v : 0.f;
    p1 += (tsub == 1) ? b1v : 0.f;
    p2 += (tsub == 2) ? b1v : 0.f;

    // butterfly over the 4-lane edge group (deterministic, all lanes get sums)
    p0 += __shfl_xor_sync(0xffffffffu, p0, 1);
    p1 += __shfl_xor_sync(0xffffffffu, p1, 1);
    p2 += __shfl_xor_sync(0xffffffffu, p2, 1);
    p0 += __shfl_xor_sync(0xffffffffu, p0, 2);
    p1 += __shfl_xor_sync(0xffffffffu, p1, 2);
    p2 += __shfl_xor_sync(0xffffffffu, p2, 2);

    const float h0 = tanh_e(p0);
    const float h1 = tanh_e(p1);
    const float h2 = tanh_e(p2);

    // --- Synapse Linear(3->1): lane tsub contributes w2[tsub]*h[tsub], lane 3: b2 ---
    float contrib = (tsub == 0) ? w2v * h0
                  : (tsub == 1) ? w2v * h1
                  : (tsub == 2) ? w2v * h2
                  : b1v;                      // lane 3: b1v == b2
    contrib += __shfl_xor_sync(0xffffffffu, contrib, 1);
    contrib += __shfl_xor_sync(0xffffffffu, contrib, 2);
    const float s = tanh_e(contrib);

    // --- aggregator partials: lane tsub<3 accumulates aW1[q,tsub,p]*s ---
    float pa = awv * s;
    pa += __shfl_down_sync(0xffffffffu, pa, 16);  // preserves tsub alignment
    pa += __shfl_down_sync(0xffffffffu, pa, 8);
    pa += __shfl_down_sync(0xffffffffu, pa, 4);
    const int lane = t & 31, w = t >> 5;
    if (lane < 3) red[lane][w] = pa;   // lane k holds warp-sum for k
    __syncthreads();

    if (t == 0) {
        // single thread writes all 3 partials -> one fence orders them all
        #pragma unroll
        for (int k = 0; k < 3; ++k) {
            float tot = 0.f;
            #pragma unroll
            for (int ww = 0; ww < TPB / 32; ++ww) tot += red[k][ww];
            g_part[(q * 3 + k) * NCHUNK + chunk] = tot;
        }
        __threadfence();
        unsigned old = atomicAdd(&g_cnt[q], 1u);
        if (old == NCHUNK - 1u) {   // last CTA for this q: epilogue
            __threadfence();        // acquire: see other CTAs' g_part writes
            float out = eb2;
            #pragma unroll
            for (int k = 0; k < 3; ++k) {
                const float* gp = &g_part[(q * 3 + k) * NCHUNK];
                float tot = oh[k] + eb1[k];
                #pragma unroll
                for (int c = 0; c < NCHUNK; ++c) tot += gp[c];
                out = fmaf(ew2[k], tanh_e(tot), out);
            }
            if (dout) dout[NN - 1 - q] = out;   // final layer: reversed
            else      g_act[out_buf][q] = out;
            g_cnt[q] = 0u;                      // reset for next layer / replay
        }
    }
}

extern "C" void kernel_launch(void* const* d_in, const int* in_sizes, int n_in,
                              void* d_out, int out_size)
{
    const float* x      = (const float*)d_in[0];
    const float* vec_W  = (const float*)d_in[1];
    const float* vec_b  = (const float*)d_in[2];
    const float* syn_W1 = (const float*)d_in[3];
    const float* syn_b1 = (const float*)d_in[4];
    const float* syn_W2 = (const float*)d_in[5];
    const float* syn_b2 = (const float*)d_in[6];
    const float* agg_W1 = (const float*)d_in[7];
    const float* agg_b1 = (const float*)d_in[8];
    const float* agg_W2 = (const float*)d_in[9];
    const float* agg_b2 = (const float*)d_in[10];
    float* out = (float*)d_out;

    const size_t VEC_L = (size_t)NN * NN * CC;
    const size_t SW1_L = (size_t)NN * NN * 48;
    const size_t SB1_L = (size_t)NN * NN * 3;
    const size_t SB2_L = (size_t)NN * NN;
    const size_t AW1_L = (size_t)NN * 3 * AGG_IN;
    const size_t AB1_L = (size_t)NN * 3;   // stride for agg_b1 AND agg_W2 (both (LT,N,3))
    const size_t AB2_L = (size_t)NN;       // stride for agg_b2 (LT,N)

    const int NCTA = (NN * NN) / 64;    // 4096 (64 edges per CTA)

    for (int l = 0; l < LTL; ++l) {
        const float* a_ext = (l == 0) ? x : nullptr;
        const int in_buf  = (l == 1) ? 0 : 1;
        const int out_buf = (l == 0) ? 0 : 1;
        float* dw = (l == LTL - 1) ? out : nullptr;

        edge_kernel<<<NCTA, TPB>>>(
            a_ext, in_buf, out_buf, l, dw,
            vec_W  + (size_t)l * VEC_L,  vec_b  + (size_t)l * VEC_L,
            syn_W1 + (size_t)l * SW1_L,  syn_b1 + (size_t)l * SB1_L,
            syn_W2 + (size_t)l * SB1_L,  syn_b2 + (size_t)l * SB2_L,
            agg_W1 + (size_t)l * AW1_L,  agg_b1 + (size_t)l * AB1_L,
            agg_W2 + (size_t)l * AB1_L,  agg_b2 + (size_t)l * AB2_L);
    }
}